// round 16
// baseline (speedup 1.0000x reference)
#include <cuda_runtime.h>

// x: (B=64, NU=32, IC=256, UNIT=128) fp32, contiguous.
// Reference reinterprets flat buffer as (B, IC, NU, UNIT):
//   u_hat[b,i,j,u] = x_flat[b*1048576 + i*4096 + j*128 + u]
// s[b,j,u] = (1/256) * sum_i u_hat[b,i,j,u]; then squash over u (128 elems).
// Output: (B, NU, UNIT) = 262144 fp32.
//
// FINAL champion (converged; do not edit). 256-thread blocks (8 warps),
// one block per (b,j) group (2048 blocks). Warps i-INTERLEAVED
// (i = warp + 8k): block live window = 8 CONSECUTIVE 16KB rows x 512B
// (measured optimum; 4-row slower, 16-row equal). Dual independent
// accumulators, fully unrolled 16-iter k-loop, __launch_bounds__(256,4)
// (64-reg budget), __ldcs read-once streaming. Smem combine + warp-0
// squash epilogue.
//
// Session evidence (15 rounds, 14 variants): concurrency, wave shape,
// persistent blocks, request width (512B/1KB), sequential-vs-strided
// streams, reg/MLP budget, accumulator depth, row-window size (4/8/16),
// LDG.128 vs LDG.256, and unroll depth all measured. Every structure
// converges at 6.35-6.54 TB/s (~81% of 8TB/s spec) — the platform's
// practical fp32-stream ceiling at NAT clocks (a perfectly sequential
// stream hit the same number, so the limit is path-level, not
// pattern-level). Champion benches: 43.04/43.07/43.10/43.49 us; ncu
// kernel dur 41.6-42.9 us vs the ~41.0 us bandwidth floor.

static constexpr int IC       = 256;
static constexpr int GROUPS   = 64 * 32;        // 2048 blocks
static constexpr int STRIDE4  = 4096 / 4;       // i-stride in float4 units
static constexpr int THREADS  = 256;            // 8 warps/block
static constexpr int IC_PER_W = IC / 8;         // 32 rows per warp

__global__ __launch_bounds__(THREADS, 4)
void capsule_squash_kernel(const float4* __restrict__ x4,
                           float4* __restrict__ out4) {
    const int g    = blockIdx.x;                // group = b*32 + j
    const int warp = threadIdx.x >> 5;
    const int lane = threadIdx.x & 31;

    const int b = g >> 5;
    const int j = g & 31;
    // warp w reads rows i = w, w+8, w+16, ... (interleaved across 8 warps)
    const int base4 = b * (1048576 / 4) + j * (128 / 4) + lane
                    + warp * STRIDE4;

    float4 sA = make_float4(0.f, 0.f, 0.f, 0.f);
    float4 sB = make_float4(0.f, 0.f, 0.f, 0.f);

#pragma unroll
    for (int k = 0; k < IC_PER_W; k += 2) {
        float4 vA = __ldcs(&x4[base4 + (k    ) * (8 * STRIDE4)]);
        float4 vB = __ldcs(&x4[base4 + (k + 1) * (8 * STRIDE4)]);
        sA.x += vA.x; sA.y += vA.y; sA.z += vA.z; sA.w += vA.w;
        sB.x += vB.x; sB.y += vB.y; sB.z += vB.z; sB.w += vB.w;
    }
    float4 s = make_float4(sA.x + sB.x, sA.y + sB.y,
                           sA.z + sB.z, sA.w + sB.w);

    __shared__ float4 part[8][32];
    part[warp][lane] = s;
    __syncthreads();

    if (warp == 0) {
        float4 t = part[0][lane];
#pragma unroll
        for (int w = 1; w < 8; w++) {
            float4 p = part[w][lane];
            t.x += p.x; t.y += p.y; t.z += p.z; t.w += p.w;
        }
        const float c = 1.0f / 256.0f;
        t.x *= c; t.y *= c; t.z *= c; t.w *= c;

        // mag_sq over the 128-element unit dim (warp-wide)
        float sq = t.x * t.x + t.y * t.y + t.z * t.z + t.w * t.w;
#pragma unroll
        for (int off = 16; off > 0; off >>= 1)
            sq += __shfl_xor_sync(0xffffffffu, sq, off);

        const float mag   = sqrtf(sq);
        const float scale = sq / (1.0f + sq) / (mag + 1e-5f);

        out4[g * 32 + lane] = make_float4(t.x * scale, t.y * scale,
                                          t.z * scale, t.w * scale);
    }
}

extern "C" void kernel_launch(void* const* d_in, const int* in_sizes, int n_in,
                              void* d_out, int out_size) {
    const float4* x4 = (const float4*)d_in[0];
    float4* out4 = (float4*)d_out;
    capsule_squash_kernel<<<GROUPS, THREADS>>>(x4, out4);
}

// round 17
// speedup vs baseline: 1.0007x; 1.0007x over previous
#include <cuda_runtime.h>

// x: (B=64, NU=32, IC=256, UNIT=128) fp32, contiguous.
// Reference reinterprets flat buffer as (B, IC, NU, UNIT):
//   u_hat[b,i,j,u] = x_flat[b*1048576 + i*4096 + j*128 + u]
// s[b,j,u] = (1/256) * sum_i u_hat[b,i,j,u]; then squash over u (128 elems).
// Output: (B, NU, UNIT) = 262144 fp32.
//
// FINAL champion (converged — 5x reproduced, do not edit).
// 256-thread blocks (8 warps), one block per (b,j) group (2048 blocks).
// Warps i-INTERLEAVED (i = warp + 8k): block live window = 8 CONSECUTIVE
// 16KB rows x 512B (measured optimum; 4-row slower, 16-row equal).
// Dual independent accumulators, fully unrolled k-loop,
// __launch_bounds__(256,4) (64-reg budget), __ldcs read-once streaming.
// Smem combine + warp-0 squash epilogue.
//
// Session evidence (16 rounds, 14 variants): concurrency, wave shape,
// persistent blocks, request width, sequential-vs-strided streams,
// reg/MLP budget, accumulator depth, row-window size (4/8/16),
// LDG.128 vs LDG.256, unroll depth — all measured; all converge at
// 6.35-6.54 TB/s (~81% of 8TB/s spec), the platform's practical
// fp32-stream ceiling at NAT clocks (path-level, not pattern-level:
// a perfectly sequential stream hit the same number).
// Champion: bench 43.04-43.49us over 5 runs; ncu kernel 41.6us vs the
// 41.0us bandwidth floor at the observed ceiling (~98.5%).

static constexpr int IC       = 256;
static constexpr int GROUPS   = 64 * 32;        // 2048 blocks
static constexpr int STRIDE4  = 4096 / 4;       // i-stride in float4 units
static constexpr int THREADS  = 256;            // 8 warps/block
static constexpr int IC_PER_W = IC / 8;         // 32 rows per warp

__global__ __launch_bounds__(THREADS, 4)
void capsule_squash_kernel(const float4* __restrict__ x4,
                           float4* __restrict__ out4) {
    const int g    = blockIdx.x;                // group = b*32 + j
    const int warp = threadIdx.x >> 5;
    const int lane = threadIdx.x & 31;

    const int b = g >> 5;
    const int j = g & 31;
    // warp w reads rows i = w, w+8, w+16, ... (interleaved across 8 warps)
    const int base4 = b * (1048576 / 4) + j * (128 / 4) + lane
                    + warp * STRIDE4;

    float4 sA = make_float4(0.f, 0.f, 0.f, 0.f);
    float4 sB = make_float4(0.f, 0.f, 0.f, 0.f);

#pragma unroll
    for (int k = 0; k < IC_PER_W; k += 2) {
        float4 vA = __ldcs(&x4[base4 + (k    ) * (8 * STRIDE4)]);
        float4 vB = __ldcs(&x4[base4 + (k + 1) * (8 * STRIDE4)]);
        sA.x += vA.x; sA.y += vA.y; sA.z += vA.z; sA.w += vA.w;
        sB.x += vB.x; sB.y += vB.y; sB.z += vB.z; sB.w += vB.w;
    }
    float4 s = make_float4(sA.x + sB.x, sA.y + sB.y,
                           sA.z + sB.z, sA.w + sB.w);

    __shared__ float4 part[8][32];
    part[warp][lane] = s;
    __syncthreads();

    if (warp == 0) {
        float4 t = part[0][lane];
#pragma unroll
        for (int w = 1; w < 8; w++) {
            float4 p = part[w][lane];
            t.x += p.x; t.y += p.y; t.z += p.z; t.w += p.w;
        }
        const float c = 1.0f / 256.0f;
        t.x *= c; t.y *= c; t.z *= c; t.w *= c;

        // mag_sq over the 128-element unit dim (warp-wide)
        float sq = t.x * t.x + t.y * t.y + t.z * t.z + t.w * t.w;
#pragma unroll
        for (int off = 16; off > 0; off >>= 1)
            sq += __shfl_xor_sync(0xffffffffu, sq, off);

        const float mag   = sqrtf(sq);
        const float scale = sq / (1.0f + sq) / (mag + 1e-5f);

        out4[g * 32 + lane] = make_float4(t.x * scale, t.y * scale,
                                          t.z * scale, t.w * scale);
    }
}

extern "C" void kernel_launch(void* const* d_in, const int* in_sizes, int n_in,
                              void* d_out, int out_size) {
    const float4* x4 = (const float4*)d_in[0];
    float4* out4 = (float4*)d_out;
    capsule_squash_kernel<<<GROUPS, THREADS>>>(x4, out4);
}